// round 2
// baseline (speedup 1.0000x reference)
#include <cuda_runtime.h>

#define D 128
#define MAXN 100000
#define MAXE 1600000

// ---------------- device scratch (no allocations allowed) ----------------
__device__ int   g_cnt[MAXN];
__device__ int   g_rowptr[MAXN + 1];
__device__ int   g_cursor[MAXN];
__device__ int   g_csr[MAXE];
__device__ float g_dinv[MAXN];
__device__ float g_h[(size_t)MAXN * D];   // layer dense output
__device__ float g_x[(size_t)MAXN * D];   // layer-1 activation

// ---------------- packed f32x2 helpers (FFMA2) ----------------
__device__ __forceinline__ unsigned long long pack2(float x, float y) {
    unsigned long long r;
    asm("mov.b64 %0, {%1, %2};" : "=l"(r) : "f"(x), "f"(y));
    return r;
}
__device__ __forceinline__ void unpack2(unsigned long long v, float& x, float& y) {
    asm("mov.b64 {%0, %1}, %2;" : "=f"(x), "=f"(y) : "l"(v));
}
__device__ __forceinline__ void ffma2(unsigned long long& acc,
                                      unsigned long long a, unsigned long long b) {
    asm("fma.rn.f32x2 %0, %1, %2, %0;" : "+l"(acc) : "l"(a), "l"(b));
}

// ---------------- CSR build ----------------
__global__ void zero_cnt_k(int n) {
    int i = blockIdx.x * blockDim.x + threadIdx.x;
    if (i < n) g_cnt[i] = 0;
}

__global__ void count_k(const int* __restrict__ dst, int E) {
    int i = blockIdx.x * blockDim.x + threadIdx.x;
    if (i < E) atomicAdd(&g_cnt[dst[i]], 1);
}

// single-block exclusive scan of g_cnt -> g_rowptr (n up to 100k)
__global__ void scan_k(int n) {
    __shared__ int buf[1024];
    __shared__ int carry;
    int tid = threadIdx.x;
    if (tid == 0) carry = 0;
    __syncthreads();
    for (int base = 0; base < n; base += 1024) {
        int i = base + tid;
        int v = (i < n) ? g_cnt[i] : 0;
        buf[tid] = v;
        __syncthreads();
        for (int off = 1; off < 1024; off <<= 1) {
            int t = (tid >= off) ? buf[tid - off] : 0;
            __syncthreads();
            buf[tid] += t;
            __syncthreads();
        }
        int c = carry;
        if (i < n) g_rowptr[i] = c + buf[tid] - v;   // exclusive
        __syncthreads();
        if (tid == 0) carry = c + buf[1023];
        __syncthreads();
    }
    if (threadIdx.x == 0) g_rowptr[n] = carry;
}

__global__ void dinv_cursor_k(int n) {
    int i = blockIdx.x * blockDim.x + threadIdx.x;
    if (i < n) {
        g_dinv[i] = rsqrtf((float)(g_cnt[i] + 1));   // +1 self-loop
        g_cursor[i] = g_rowptr[i];
    }
}

__global__ void fill_k(const int* __restrict__ src, const int* __restrict__ dst, int E) {
    int i = blockIdx.x * blockDim.x + threadIdx.x;
    if (i < E) {
        int p = atomicAdd(&g_cursor[dst[i]], 1);
        g_csr[p] = src[i];
    }
}

// ---------------- dense transform: g_h = X @ W ----------------
// 256 threads (8 warps); warp handles 4 rows, lane handles 4 consecutive cols.
__global__ void gemm_k(const float* __restrict__ X, const float* __restrict__ W, int n) {
    extern __shared__ float sm[];
    float*  sW  = sm;             // 128*128
    float*  sX  = sm + D * D;     // 32*128
    float4* sW4 = (float4*)sW;
    float4* sX4 = (float4*)sX;
    int tid = threadIdx.x;

    const float4* W4 = (const float4*)W;
    for (int i = tid; i < D * D / 4; i += 256) sW4[i] = W4[i];

    int row0 = blockIdx.x * 32;
    for (int i = tid; i < 32 * D / 4; i += 256) {
        int r = row0 + i / (D / 4);
        sX4[i] = (r < n) ? ((const float4*)X)[(size_t)row0 * (D / 4) + i]
                         : make_float4(0.f, 0.f, 0.f, 0.f);
    }
    __syncthreads();

    int warp = tid >> 5, lane = tid & 31;
    int rb = warp * 4;
    unsigned long long a01[4] = {0, 0, 0, 0};
    unsigned long long a23[4] = {0, 0, 0, 0};

    #pragma unroll 4
    for (int k = 0; k < D; k++) {
        float4 wv = sW4[k * 32 + lane];                 // conflict-free
        unsigned long long w01 = pack2(wv.x, wv.y);
        unsigned long long w23 = pack2(wv.z, wv.w);
        #pragma unroll
        for (int r = 0; r < 4; r++) {
            float xk = sX[(rb + r) * D + k];            // broadcast
            unsigned long long xx = pack2(xk, xk);
            ffma2(a01[r], xx, w01);
            ffma2(a23[r], xx, w23);
        }
    }

    #pragma unroll
    for (int r = 0; r < 4; r++) {
        int row = row0 + rb + r;
        if (row < n) {
            float4 o;
            unpack2(a01[r], o.x, o.y);
            unpack2(a23[r], o.z, o.w);
            ((float4*)g_h)[(size_t)row * 32 + lane] = o;
        }
    }
}

// ---------------- aggregation: out = relu(agg + h), warp per node ----------------
__global__ void agg_k(float4* __restrict__ out, int n) {
    int t = blockIdx.x * blockDim.x + threadIdx.x;
    int node = t >> 5;
    int lane = t & 31;
    if (node >= n) return;

    const float4* h4 = (const float4*)g_h;
    float dv = g_dinv[node];
    float4 hv = h4[(size_t)node * 32 + lane];
    float ws = dv * dv;                                  // self-loop norm
    float4 acc = make_float4(ws * hv.x, ws * hv.y, ws * hv.z, ws * hv.w);

    int s = g_rowptr[node], e = g_rowptr[node + 1];
    int i = s;
    for (; i + 3 < e; i += 4) {
        int u0 = g_csr[i], u1 = g_csr[i + 1], u2 = g_csr[i + 2], u3 = g_csr[i + 3];
        float w0 = g_dinv[u0] * dv, w1 = g_dinv[u1] * dv;
        float w2 = g_dinv[u2] * dv, w3 = g_dinv[u3] * dv;
        float4 v0 = h4[(size_t)u0 * 32 + lane];
        float4 v1 = h4[(size_t)u1 * 32 + lane];
        float4 v2 = h4[(size_t)u2 * 32 + lane];
        float4 v3 = h4[(size_t)u3 * 32 + lane];
        acc.x += w0 * v0.x + w1 * v1.x + w2 * v2.x + w3 * v3.x;
        acc.y += w0 * v0.y + w1 * v1.y + w2 * v2.y + w3 * v3.y;
        acc.z += w0 * v0.z + w1 * v1.z + w2 * v2.z + w3 * v3.z;
        acc.w += w0 * v0.w + w1 * v1.w + w2 * v2.w + w3 * v3.w;
    }
    for (; i < e; i++) {
        int u = g_csr[i];
        float w = g_dinv[u] * dv;
        float4 v = h4[(size_t)u * 32 + lane];
        acc.x += w * v.x; acc.y += w * v.y; acc.z += w * v.z; acc.w += w * v.w;
    }

    out[(size_t)node * 32 + lane] = make_float4(
        fmaxf(acc.x + hv.x, 0.f), fmaxf(acc.y + hv.y, 0.f),
        fmaxf(acc.z + hv.z, 0.f), fmaxf(acc.w + hv.w, 0.f));
}

// ---------------- seed gather: warp per seed ----------------
__global__ void gather_k(const int* __restrict__ seeds, const float4* __restrict__ ent,
                         float4* __restrict__ out, int ns) {
    int t = blockIdx.x * blockDim.x + threadIdx.x;
    int s = t >> 5;
    int lane = t & 31;
    if (s < ns) out[(size_t)s * 32 + lane] = ent[(size_t)seeds[s] * 32 + lane];
}

// ---------------- launch ----------------
extern "C" void kernel_launch(void* const* d_in, const int* in_sizes, int n_in,
                              void* d_out, int out_size) {
    const int*   seeds_sr = (const int*)d_in[0];
    const int*   seeds_tg = (const int*)d_in[1];
    const int*   edges_sr = (const int*)d_in[2];
    const int*   edges_tg = (const int*)d_in[3];
    const float* emb_sr   = (const float*)d_in[4];
    const float* emb_tg   = (const float*)d_in[5];
    const float* W0       = (const float*)d_in[6];
    const float* W1       = (const float*)d_in[7];

    int S = in_sizes[0];
    int E = in_sizes[2] / 2;
    int N = in_sizes[4] / D;

    float* out     = (float*)d_out;
    float* sr_seed = out;
    float* tg_seed = sr_seed + (size_t)S * D;
    float* sr_ent  = tg_seed + (size_t)S * D;
    float* tg_ent  = sr_ent  + (size_t)N * D;

    void* xaddr = nullptr;
    cudaGetSymbolAddress(&xaddr, g_x);

    int smem = (D * D + 32 * D) * (int)sizeof(float);   // 80 KB
    cudaFuncSetAttribute(gemm_k, cudaFuncAttributeMaxDynamicSharedMemorySize, smem);

    for (int g = 0; g < 2; g++) {
        const int*   edges = g ? edges_tg : edges_sr;
        const float* emb   = g ? emb_tg   : emb_sr;
        const int*   seeds = g ? seeds_tg : seeds_sr;
        float* ent      = g ? tg_ent  : sr_ent;
        float* seed_out = g ? tg_seed : sr_seed;
        const int* src = edges;
        const int* dst = edges + E;

        // CSR build (by destination) + symmetric-norm dinv
        zero_cnt_k<<<(N + 255) / 256, 256>>>(N);
        count_k<<<(E + 255) / 256, 256>>>(dst, E);
        scan_k<<<1, 1024>>>(N);
        dinv_cursor_k<<<(N + 255) / 256, 256>>>(N);
        fill_k<<<(E + 255) / 256, 256>>>(src, dst, E);

        // layer 1: h = emb @ W0 ; x = relu(agg(h) + h)
        gemm_k<<<(N + 31) / 32, 256, smem>>>(emb, W0, N);
        agg_k<<<((size_t)N * 32 + 255) / 256, 256>>>((float4*)xaddr, N);

        // layer 2: h = x @ W1 ; ent = relu(agg(h) + h)
        gemm_k<<<(N + 31) / 32, 256, smem>>>((const float*)xaddr, W1, N);
        agg_k<<<((size_t)N * 32 + 255) / 256, 256>>>((float4*)ent, N);

        // seed gather
        gather_k<<<((size_t)S * 32 + 255) / 256, 256>>>(seeds, (const float4*)ent,
                                                        (float4*)seed_out, S);
    }
}